// round 3
// baseline (speedup 1.0000x reference)
#include <cuda_runtime.h>
#include <cuda_bf16.h>

// ---------------------------------------------------------------------------
// PhysicsProjection fused kernel (Round 1 baseline resubmit: fp32 SIMT,
// f32x2 packed FMA). Round-2 bench was an infra failure; no metric signal.
//
// Tokens: per row of x[16384,111]:
//   17 pv  slices (din=3)  -> shared MLP (Lin->LN->GELU->Lin)
//    2 rot slices (din=9)  -> shared MLP
//    2 st  slices (din=4)  -> full MLP (…->Lin->LN)
//    1 pad slice  (din=34) -> full MLP
// Output row = 22 slots of 256 + raw x (111)  => 5743 floats.
// ---------------------------------------------------------------------------

#define NROWS 16384
#define NX    111
#define DMODEL 256
#define OUT_STRIDE (22 * 256 + 111)   // 5743
#define TOK_PER_CTA 64

// block ranges per type
#define PV_BLOCKS  4352   // 16384*17/64
#define ROT_BLOCKS 512    // 16384*2/64
#define ST_BLOCKS  512
#define PAD_BLOCKS 256
#define TOTAL_BLOCKS (PV_BLOCKS + ROT_BLOCKS + ST_BLOCKS + PAD_BLOCKS) // 5632

__constant__ int c_PV_START[17] = {0,3,6,43,46,49,61,64,67,74,77,80,92,95,98,105,108};
__constant__ int c_PV_SLOT[17]  = {0,1,2,4,5,6,8,9,10,12,13,14,16,17,18,20,21};

// smem layout (floats)
#define S_XS    0                 // [64][35]            2240
#define S_W1    (S_XS + 2240)     // [34][256]           8704
#define S_B1    (S_W1 + 8704)     // 256
#define S_G1    (S_B1 + 256)
#define S_BT1   (S_G1 + 256)
#define S_B2    (S_BT1 + 256)
#define S_G2    (S_B2 + 256)
#define S_BT2   (S_G2 + 256)
#define S_A     (S_BT2 + 256)     // [64][257]          16448
#define S_BT    (S_A + 16448)     // [32][256]           8192
#define S_BASE  (S_BT + 8192)     // 64 ints (as float slots)
#define SMEM_FLOATS (S_BASE + 64)
#define SMEM_BYTES (SMEM_FLOATS * 4)

struct Params {
    const float* x;
    const float* W1[4];
    const float* b1[4];
    const float* g1[4];
    const float* bt1[4];
    const float* W2[4];
    const float* b2[4];
    const float* g2[4];   // null for types 0,1
    const float* bt2[4];
    float* out;
};

// ---- packed f32x2 helpers (sm_100+) ----
__device__ __forceinline__ unsigned long long ffma2(unsigned long long a,
                                                    unsigned long long b,
                                                    unsigned long long c) {
    unsigned long long d;
    asm("fma.rn.f32x2 %0, %1, %2, %3;" : "=l"(d) : "l"(a), "l"(b), "l"(c));
    return d;
}
__device__ __forceinline__ unsigned long long dup2(float a) {
    unsigned long long d;
    asm("mov.b64 %0, {%1, %1};" : "=l"(d) : "f"(a));
    return d;
}
__device__ __forceinline__ unsigned long long pack2(float lo, float hi) {
    unsigned long long d;
    asm("mov.b64 %0, {%1, %2};" : "=l"(d) : "f"(lo), "f"(hi));
    return d;
}
__device__ __forceinline__ void unpack2(unsigned long long v, float& lo, float& hi) {
    asm("mov.b64 {%0, %1}, %2;" : "=f"(lo), "=f"(hi) : "l"(v));
}

// LN (+ optional exact GELU) over 256 cols, in-place in smem A[64][257].
// 8 warps, each owns 8 tokens.
__device__ __forceinline__ void ln_pass(float* A, const float* g, const float* b,
                                        bool gelu) {
    const int warp = threadIdx.x >> 5;
    const int lane = threadIdx.x & 31;
    #pragma unroll
    for (int r = 0; r < 8; ++r) {
        const int tok = warp * 8 + r;
        float v[8];
        float s = 0.f, s2 = 0.f;
        #pragma unroll
        for (int c = 0; c < 8; ++c) {
            v[c] = A[tok * 257 + lane + (c << 5)];
            s += v[c];
            s2 += v[c] * v[c];
        }
        #pragma unroll
        for (int o = 16; o > 0; o >>= 1) {
            s  += __shfl_xor_sync(0xffffffffu, s, o);
            s2 += __shfl_xor_sync(0xffffffffu, s2, o);
        }
        const float mean = s * (1.0f / 256.0f);
        const float var  = s2 * (1.0f / 256.0f) - mean * mean;
        const float rstd = rsqrtf(var + 1e-5f);
        #pragma unroll
        for (int c = 0; c < 8; ++c) {
            const int j = lane + (c << 5);
            float t = (v[c] - mean) * rstd * g[j] + b[j];
            if (gelu)
                t = 0.5f * t * (1.0f + erff(t * 0.70710678118654752f));
            A[tok * 257 + j] = t;
        }
    }
}

template <int DIN>
__device__ __forceinline__ void first_linear(const float* xs, const float* w1s,
                                             const float* b1s, float* A) {
    const int j = threadIdx.x;  // 0..255
    #pragma unroll 4
    for (int tok = 0; tok < TOK_PER_CTA; ++tok) {
        float acc = b1s[j];
        #pragma unroll
        for (int i = 0; i < DIN; ++i)
            acc += xs[tok * 35 + i] * w1s[i * 256 + j];
        A[tok * 257 + j] = acc;
    }
}

__global__ void __launch_bounds__(256, 1)
phys_kernel(Params p) {
    extern __shared__ float smem[];
    float* xs  = smem + S_XS;
    float* w1s = smem + S_W1;
    float* b1s = smem + S_B1;
    float* g1s = smem + S_G1;
    float* bt1s = smem + S_BT1;
    float* b2s = smem + S_B2;
    float* g2s = smem + S_G2;
    float* bt2s = smem + S_BT2;
    float* A   = smem + S_A;
    float* Bt  = smem + S_BT;
    int* baseS = reinterpret_cast<int*>(smem + S_BASE);

    const int tid = threadIdx.x;
    const int bid = blockIdx.x;

    int type, tokBase;
    if (bid < PV_BLOCKS)                      { type = 0; tokBase = bid * TOK_PER_CTA; }
    else if (bid < PV_BLOCKS + ROT_BLOCKS)    { type = 1; tokBase = (bid - PV_BLOCKS) * TOK_PER_CTA; }
    else if (bid < PV_BLOCKS + ROT_BLOCKS + ST_BLOCKS)
                                              { type = 2; tokBase = (bid - PV_BLOCKS - ROT_BLOCKS) * TOK_PER_CTA; }
    else                                      { type = 3; tokBase = (bid - PV_BLOCKS - ROT_BLOCKS - ST_BLOCKS) * TOK_PER_CTA; }

    const int din = (type == 0) ? 3 : (type == 1) ? 9 : (type == 2) ? 4 : 34;
    const bool hasLN2 = (type >= 2);

    // ---- load per-type parameters ----
    b1s[tid]  = p.b1[type][tid];
    g1s[tid]  = p.g1[type][tid];
    bt1s[tid] = p.bt1[type][tid];
    b2s[tid]  = p.b2[type][tid];
    if (hasLN2) {
        g2s[tid]  = p.g2[type][tid];
        bt2s[tid] = p.bt2[type][tid];
    }
    for (int idx = tid; idx < din * 256; idx += 256)
        w1s[idx] = p.W1[type][idx];

    // ---- per-token output base offsets ----
    if (tid < TOK_PER_CTA) {
        const int t = tokBase + tid;
        int row, slot;
        if (type == 0)      { row = t / 17; slot = c_PV_SLOT[t - row * 17]; }
        else if (type == 1) { row = t >> 1; slot = (t & 1) ? 15 : 7; }
        else if (type == 2) { row = t >> 1; slot = (t & 1) ? 19 : 11; }
        else                { row = t;      slot = 3; }
        baseS[tid] = row * OUT_STRIDE + slot * 256;
    }

    // ---- gather input features ----
    const int totalFeat = TOK_PER_CTA * din;
    for (int idx = tid; idx < totalFeat; idx += 256) {
        const int tok = idx / din;
        const int i   = idx - tok * din;
        const int t   = tokBase + tok;
        int row, col;
        if (type == 0)      { row = t / 17; col = c_PV_START[t - row * 17] + i; }
        else if (type == 1) { row = t >> 1; col = ((t & 1) ? 83 : 52) + i; }
        else if (type == 2) { row = t >> 1; col = ((t & 1) ? 101 : 70) + i; }
        else                { row = t;      col = 9 + i; }
        xs[tok * 35 + i] = p.x[row * NX + col];
    }
    __syncthreads();

    // ---- Linear1 ----
    if (type == 0)      first_linear<3>(xs, w1s, b1s, A);
    else if (type == 1) first_linear<9>(xs, w1s, b1s, A);
    else if (type == 2) first_linear<4>(xs, w1s, b1s, A);
    else                first_linear<34>(xs, w1s, b1s, A);
    __syncthreads();

    // ---- LN + GELU ----
    ln_pass(A, g1s, bt1s, true);
    __syncthreads();

    // ---- GEMM: C[64,256] = A[64,256] @ W2[256,256] ----
    const int tn = tid & 15;
    const int tm = tid >> 4;
    const int m0 = tm * 4;
    const float* W2 = p.W2[type];

    unsigned long long acc[4][4][2];
    #pragma unroll
    for (int mi = 0; mi < 4; ++mi)
        #pragma unroll
        for (int g = 0; g < 4; ++g) {
            acc[mi][g][0] = 0ull;
            acc[mi][g][1] = 0ull;
        }

    for (int kc = 0; kc < 8; ++kc) {
        __syncthreads();
        {
            const float4* src = reinterpret_cast<const float4*>(W2 + kc * 8192);
            float4* dst = reinterpret_cast<float4*>(Bt);
            #pragma unroll
            for (int r = 0; r < 8; ++r)
                dst[tid + (r << 8)] = src[tid + (r << 8)];
        }
        __syncthreads();
        #pragma unroll 4
        for (int kk = 0; kk < 32; ++kk) {
            const int k = (kc << 5) + kk;
            unsigned long long a2[4];
            #pragma unroll
            for (int mi = 0; mi < 4; ++mi)
                a2[mi] = dup2(A[(m0 + mi) * 257 + k]);
            const float4* brow = reinterpret_cast<const float4*>(Bt + (kk << 8));
            #pragma unroll
            for (int g = 0; g < 4; ++g) {
                const float4 bv = brow[tn + (g << 4)];
                const unsigned long long b01 = pack2(bv.x, bv.y);
                const unsigned long long b23 = pack2(bv.z, bv.w);
                #pragma unroll
                for (int mi = 0; mi < 4; ++mi) {
                    acc[mi][g][0] = ffma2(a2[mi], b01, acc[mi][g][0]);
                    acc[mi][g][1] = ffma2(a2[mi], b23, acc[mi][g][1]);
                }
            }
        }
    }
    __syncthreads();   // all reads of A done before overwrite

    // ---- epilogue: +b2, write C back into A ----
    #pragma unroll
    for (int mi = 0; mi < 4; ++mi)
        #pragma unroll
        for (int g = 0; g < 4; ++g)
            #pragma unroll
            for (int pj = 0; pj < 2; ++pj) {
                float f0, f1;
                unpack2(acc[mi][g][pj], f0, f1);
                const int n = tn * 4 + (g << 6) + pj * 2;
                A[(m0 + mi) * 257 + n]     = f0 + b2s[n];
                A[(m0 + mi) * 257 + n + 1] = f1 + b2s[n + 1];
            }
    __syncthreads();

    if (hasLN2) {
        ln_pass(A, g2s, bt2s, false);
        __syncthreads();
    }

    // ---- coalesced store into strided output slots ----
    #pragma unroll 4
    for (int tok = 0; tok < TOK_PER_CTA; ++tok)
        p.out[baseS[tok] + tid] = A[tok * 257 + tid];
}

__global__ void copy_x_kernel(const float* __restrict__ x, float* __restrict__ out) {
    const int idx = blockIdx.x * blockDim.x + threadIdx.x;
    if (idx < NROWS * NX) {
        const int row = idx / NX;
        const int c = idx - row * NX;
        out[row * OUT_STRIDE + 22 * 256 + c] = x[idx];
    }
}

extern "C" void kernel_launch(void* const* d_in, const int* in_sizes, int n_in,
                              void* d_out, int out_size) {
    (void)in_sizes; (void)n_in; (void)out_size;
    const float* x = (const float*)d_in[0];

    Params p;
    p.x = x;
    p.out = (float*)d_out;
    // type 0 = pv (d_in 1..6), 1 = rot (7..12), 2 = st (21..28), 3 = pad (13..20)
    p.W1[0] = (const float*)d_in[1];  p.b1[0] = (const float*)d_in[2];
    p.g1[0] = (const float*)d_in[3];  p.bt1[0] = (const float*)d_in[4];
    p.W2[0] = (const float*)d_in[5];  p.b2[0] = (const float*)d_in[6];
    p.g2[0] = nullptr;                p.bt2[0] = nullptr;

    p.W1[1] = (const float*)d_in[7];  p.b1[1] = (const float*)d_in[8];
    p.g1[1] = (const float*)d_in[9];  p.bt1[1] = (const float*)d_in[10];
    p.W2[1] = (const float*)d_in[11]; p.b2[1] = (const float*)d_in[12];
    p.g2[1] = nullptr;                p.bt2[1] = nullptr;

    p.W1[2] = (const float*)d_in[21]; p.b1[2] = (const float*)d_in[22];
    p.g1[2] = (const float*)d_in[23]; p.bt1[2] = (const float*)d_in[24];
    p.W2[2] = (const float*)d_in[25]; p.b2[2] = (const float*)d_in[26];
    p.g2[2] = (const float*)d_in[27]; p.bt2[2] = (const float*)d_in[28];

    p.W1[3] = (const float*)d_in[13]; p.b1[3] = (const float*)d_in[14];
    p.g1[3] = (const float*)d_in[15]; p.bt1[3] = (const float*)d_in[16];
    p.W2[3] = (const float*)d_in[17]; p.b2[3] = (const float*)d_in[18];
    p.g2[3] = (const float*)d_in[19]; p.bt2[3] = (const float*)d_in[20];

    cudaFuncSetAttribute(phys_kernel,
                         cudaFuncAttributeMaxDynamicSharedMemorySize, SMEM_BYTES);
    phys_kernel<<<TOTAL_BLOCKS, 256, SMEM_BYTES>>>(p);

    const int nCopy = NROWS * NX;
    copy_x_kernel<<<(nCopy + 255) / 256, 256>>>(x, (float*)d_out);
}

// round 6
// speedup vs baseline: 1.2063x; 1.2063x over previous
#include <cuda_runtime.h>
#include <cuda_bf16.h>
#include <cstdint>

// ---------------------------------------------------------------------------
// PhysicsProjection fused kernel — split-bf16 mma.sync GEMM (resubmit #2;
// Rounds 4 & 5 were broker-level container failures, no kernel signal).
//   Linear1 (fp32) -> LN+GELU (fp32, emits packed split-bf16 A) ->
//   C = A @ W2 via 3x mma.m16n8k16.bf16 (hi*hi + lo*hi + hi*lo) ->
//   +b2 -> optional LN2 -> packed strided store.
// ---------------------------------------------------------------------------

#define NROWS 16384
#define NX    111
#define OUT_STRIDE (22 * 256 + 111)   // 5743
#define TOK_PER_CTA 64

#define PV_BLOCKS  4352
#define ROT_BLOCKS 512
#define ST_BLOCKS  512
#define PAD_BLOCKS 256
#define TOTAL_BLOCKS (PV_BLOCKS + ROT_BLOCKS + ST_BLOCKS + PAD_BLOCKS) // 5632

#define STRIDE_A  260   // fp32 A / C row stride (words)
#define STRIDE_AP 132   // packed split-bf16 A row stride (words) -> bank = 4*row
#define STRIDE_B  20    // packed split-bf16 B row stride (words) -> bank = 20*n

__constant__ int c_PV_START[17] = {0,3,6,43,46,49,61,64,67,74,77,80,92,95,98,105,108};
__constant__ int c_PV_SLOT[17]  = {0,1,2,4,5,6,8,9,10,12,13,14,16,17,18,20,21};

// smem layout (32-bit words)
#define S_XS    0                      // [64][35]
#define S_W1    (S_XS + 2240)          // [34][256]
#define S_B1    (S_W1 + 8704)
#define S_G1    (S_B1 + 256)
#define S_BT1   (S_G1 + 256)
#define S_B2    (S_BT1 + 256)
#define S_G2    (S_B2 + 256)
#define S_BT2   (S_G2 + 256)
#define S_BASE  (S_BT2 + 256)          // 64 ints
#define S_A     (S_BASE + 64)          // [64][260] fp32 (Linear1/LN in, C out)
#define S_AH    (S_A + 64*STRIDE_A)    // [64][132] packed bf16-hi pairs
#define S_AL    (S_AH + 64*STRIDE_AP + 16)  // +16 pad -> bank offset 16 vs AH
#define S_BH    (S_AL + 64*STRIDE_AP)  // [256][20] packed bf16-hi pairs (k-chunk)
#define S_BL    (S_BH + 256*STRIDE_B + 16)
#define SMEM_WORDS (S_BL + 256*STRIDE_B)
#define SMEM_BYTES (SMEM_WORDS * 4)    // 225,408 B  (< 227 KB)

struct Params {
    const float* x;
    const float* W1[4];
    const float* b1[4];
    const float* g1[4];
    const float* bt1[4];
    const float* W2[4];
    const float* b2[4];
    const float* g2[4];
    const float* bt2[4];
    float* out;
};

// ---- helpers ----
__device__ __forceinline__ unsigned bf16x2_lo(float l0, float l1) {
    // pack {bf16(l1) high, bf16(l0) low}: PTX first source -> upper half
    unsigned w;
    asm("cvt.rn.bf16x2.f32 %0, %1, %2;" : "=r"(w) : "f"(l1), "f"(l0));
    return w;
}

__device__ __forceinline__ void mma_bf16(float* c, unsigned a0, unsigned a1,
                                         unsigned a2, unsigned a3,
                                         unsigned b0, unsigned b1) {
    asm("mma.sync.aligned.m16n8k16.row.col.f32.bf16.bf16.f32 "
        "{%0,%1,%2,%3}, {%4,%5,%6,%7}, {%8,%9}, {%0,%1,%2,%3};"
        : "+f"(c[0]), "+f"(c[1]), "+f"(c[2]), "+f"(c[3])
        : "r"(a0), "r"(a1), "r"(a2), "r"(a3), "r"(b0), "r"(b1));
}

// LN over 256 cols of A[64][260]; MODE 1: +exact GELU, emit packed split-bf16
// into Ah/Al (no fp32 writeback). MODE 0: plain LN, write back to A.
template <int MODE>
__device__ __forceinline__ void ln_pass(float* A, const float* g, const float* b,
                                        unsigned* Ah, unsigned* Al) {
    const int warp = threadIdx.x >> 5;
    const int lane = threadIdx.x & 31;
    #pragma unroll
    for (int r = 0; r < 8; ++r) {
        const int tok = warp * 8 + r;
        float v[8];
        float s = 0.f, s2 = 0.f;
        #pragma unroll
        for (int c = 0; c < 8; ++c) {
            v[c] = A[tok * STRIDE_A + lane + (c << 5)];
            s += v[c];
            s2 += v[c] * v[c];
        }
        #pragma unroll
        for (int o = 16; o > 0; o >>= 1) {
            s  += __shfl_xor_sync(0xffffffffu, s, o);
            s2 += __shfl_xor_sync(0xffffffffu, s2, o);
        }
        const float mean = s * (1.0f / 256.0f);
        const float var  = s2 * (1.0f / 256.0f) - mean * mean;
        const float rstd = rsqrtf(var + 1e-5f);
        #pragma unroll
        for (int c = 0; c < 8; ++c) {
            const int j = lane + (c << 5);
            float t = (v[c] - mean) * rstd * g[j] + b[j];
            if (MODE == 1) {
                t = 0.5f * t * (1.0f + erff(t * 0.70710678118654752f));
                // pair adjacent columns (adjacent lanes) into one k-pair word
                const float o2 = __shfl_xor_sync(0xffffffffu, t, 1);
                const float e0 = (lane & 1) ? o2 : t;   // even column value
                const float e1 = (lane & 1) ? t : o2;   // odd column value
                const unsigned u0 = __float_as_uint(e0);
                const unsigned u1 = __float_as_uint(e1);
                const int kp = (lane >> 1) + (c << 4);
                if (!(lane & 1)) {
                    Ah[tok * STRIDE_AP + kp] = __byte_perm(u0, u1, 0x7632);
                } else {
                    const float l0 = e0 - __uint_as_float(u0 & 0xFFFF0000u);
                    const float l1 = e1 - __uint_as_float(u1 & 0xFFFF0000u);
                    Al[tok * STRIDE_AP + kp] = bf16x2_lo(l0, l1);
                }
            } else {
                A[tok * STRIDE_A + j] = t;
            }
        }
    }
}

template <int DIN>
__device__ __forceinline__ void first_linear(const float* xs, const float* w1s,
                                             const float* b1s, float* A) {
    const int j = threadIdx.x;
    float w[DIN];
    #pragma unroll
    for (int i = 0; i < DIN; ++i) w[i] = w1s[i * 256 + j];
    const float bj = b1s[j];
    #pragma unroll 4
    for (int tok = 0; tok < TOK_PER_CTA; ++tok) {
        float acc = bj;
        #pragma unroll
        for (int i = 0; i < DIN; ++i)
            acc += xs[tok * 35 + i] * w[i];
        A[tok * STRIDE_A + j] = acc;
    }
}

__global__ void __launch_bounds__(256, 1)
phys_kernel(Params p) {
    extern __shared__ float smem[];
    float* xs   = smem + S_XS;
    float* w1s  = smem + S_W1;
    float* b1s  = smem + S_B1;
    float* g1s  = smem + S_G1;
    float* bt1s = smem + S_BT1;
    float* b2s  = smem + S_B2;
    float* g2s  = smem + S_G2;
    float* bt2s = smem + S_BT2;
    float* A    = smem + S_A;
    unsigned* Ah = reinterpret_cast<unsigned*>(smem + S_AH);
    unsigned* Al = reinterpret_cast<unsigned*>(smem + S_AL);
    unsigned* Bh = reinterpret_cast<unsigned*>(smem + S_BH);
    unsigned* Bl = reinterpret_cast<unsigned*>(smem + S_BL);
    int* baseS = reinterpret_cast<int*>(smem + S_BASE);

    const int tid = threadIdx.x;
    const int bid = blockIdx.x;

    int type, tokBase;
    if (bid < PV_BLOCKS)                      { type = 0; tokBase = bid * TOK_PER_CTA; }
    else if (bid < PV_BLOCKS + ROT_BLOCKS)    { type = 1; tokBase = (bid - PV_BLOCKS) * TOK_PER_CTA; }
    else if (bid < PV_BLOCKS + ROT_BLOCKS + ST_BLOCKS)
                                              { type = 2; tokBase = (bid - PV_BLOCKS - ROT_BLOCKS) * TOK_PER_CTA; }
    else                                      { type = 3; tokBase = (bid - PV_BLOCKS - ROT_BLOCKS - ST_BLOCKS) * TOK_PER_CTA; }

    const int din = (type == 0) ? 3 : (type == 1) ? 9 : (type == 2) ? 4 : 34;
    const bool hasLN2 = (type >= 2);

    // ---- per-type parameters ----
    b1s[tid]  = p.b1[type][tid];
    g1s[tid]  = p.g1[type][tid];
    bt1s[tid] = p.bt1[type][tid];
    b2s[tid]  = p.b2[type][tid];
    if (hasLN2) {
        g2s[tid]  = p.g2[type][tid];
        bt2s[tid] = p.bt2[type][tid];
    }
    for (int idx = tid; idx < din * 256; idx += 256)
        w1s[idx] = p.W1[type][idx];

    // ---- per-token output base offsets ----
    if (tid < TOK_PER_CTA) {
        const int t = tokBase + tid;
        int row, slot;
        if (type == 0)      { row = t / 17; slot = c_PV_SLOT[t - row * 17]; }
        else if (type == 1) { row = t >> 1; slot = (t & 1) ? 15 : 7; }
        else if (type == 2) { row = t >> 1; slot = (t & 1) ? 19 : 11; }
        else                { row = t;      slot = 3; }
        baseS[tid] = row * OUT_STRIDE + slot * 256;
    }

    // ---- gather input features ----
    const int totalFeat = TOK_PER_CTA * din;
    for (int idx = tid; idx < totalFeat; idx += 256) {
        const int tok = idx / din;
        const int i   = idx - tok * din;
        const int t   = tokBase + tok;
        int row, col;
        if (type == 0)      { row = t / 17; col = c_PV_START[t - row * 17] + i; }
        else if (type == 1) { row = t >> 1; col = ((t & 1) ? 83 : 52) + i; }
        else if (type == 2) { row = t >> 1; col = ((t & 1) ? 101 : 70) + i; }
        else                { row = t;      col = 9 + i; }
        xs[tok * 35 + i] = p.x[row * NX + col];
    }
    __syncthreads();

    // ---- Linear1 ----
    if (type == 0)      first_linear<3>(xs, w1s, b1s, A);
    else if (type == 1) first_linear<9>(xs, w1s, b1s, A);
    else if (type == 2) first_linear<4>(xs, w1s, b1s, A);
    else                first_linear<34>(xs, w1s, b1s, A);
    __syncthreads();

    // ---- LN + GELU -> packed split-bf16 A ----
    ln_pass<1>(A, g1s, bt1s, Ah, Al);

    // ---- GEMM: C[64,256] = A @ W2, split-bf16, mma.m16n8k16 ----
    const int lane = tid & 31;
    const int warp = tid >> 5;
    const int wm = warp >> 2;       // 0..1 : rows wm*32..wm*32+31
    const int wn = warp & 3;        // 0..3 : cols wn*64..wn*64+63
    const int gid = lane >> 2;
    const int tig = lane & 3;
    const float* W2 = p.W2[type];

    float acc[2][8][4];
    #pragma unroll
    for (int mt = 0; mt < 2; ++mt)
        #pragma unroll
        for (int nt = 0; nt < 8; ++nt)
            #pragma unroll
            for (int q = 0; q < 4; ++q) acc[mt][nt][q] = 0.f;

    const int kpStage = tid & 15;          // staging: k-pair within chunk
    const int nStage  = (tid >> 4) << 4;   // staging: 16-col n group

    for (int chunk = 0; chunk < 8; ++chunk) {
        __syncthreads();   // prev chunk's mma done (also orders ln writes, chunk 0)
        // stage W2 chunk [k=chunk*32 .. +31][n 0..255] -> transposed packed split-bf16
        {
            const float* src = W2 + (chunk * 32 + kpStage * 2) * 256 + nStage;
            float4 r0[4], r1[4];
            #pragma unroll
            for (int i = 0; i < 4; ++i) {
                r0[i] = reinterpret_cast<const float4*>(src)[i];
                r1[i] = reinterpret_cast<const float4*>(src + 256)[i];
            }
            const float* f0 = reinterpret_cast<const float*>(r0);
            const float* f1 = reinterpret_cast<const float*>(r1);
            #pragma unroll
            for (int j = 0; j < 16; ++j) {
                const float e0 = f0[j], e1 = f1[j];
                const unsigned u0 = __float_as_uint(e0);
                const unsigned u1 = __float_as_uint(e1);
                const int addr = (nStage + j) * STRIDE_B + kpStage;
                Bh[addr] = __byte_perm(u0, u1, 0x7632);
                const float l0 = e0 - __uint_as_float(u0 & 0xFFFF0000u);
                const float l1 = e1 - __uint_as_float(u1 & 0xFFFF0000u);
                Bl[addr] = bf16x2_lo(l0, l1);
            }
        }
        __syncthreads();

        #pragma unroll
        for (int s = 0; s < 2; ++s) {      // two k16 steps per k32 chunk
            const int kp0 = chunk * 16 + 8 * s + tig;   // global A k-pair
            const int kl  = 8 * s + tig;                // chunk-local B k-pair
            unsigned ah[2][4], al[2][4];
            #pragma unroll
            for (int mt = 0; mt < 2; ++mt) {
                const int mrow = wm * 32 + mt * 16;
                ah[mt][0] = Ah[(mrow + gid)     * STRIDE_AP + kp0];
                ah[mt][1] = Ah[(mrow + gid + 8) * STRIDE_AP + kp0];
                ah[mt][2] = Ah[(mrow + gid)     * STRIDE_AP + kp0 + 4];
                ah[mt][3] = Ah[(mrow + gid + 8) * STRIDE_AP + kp0 + 4];
                al[mt][0] = Al[(mrow + gid)     * STRIDE_AP + kp0];
                al[mt][1] = Al[(mrow + gid + 8) * STRIDE_AP + kp0];
                al[mt][2] = Al[(mrow + gid)     * STRIDE_AP + kp0 + 4];
                al[mt][3] = Al[(mrow + gid + 8) * STRIDE_AP + kp0 + 4];
            }
            #pragma unroll
            for (int nt = 0; nt < 8; ++nt) {
                const int n = wn * 64 + nt * 8 + gid;
                const unsigned bh0 = Bh[n * STRIDE_B + kl];
                const unsigned bh1 = Bh[n * STRIDE_B + kl + 4];
                const unsigned bl0 = Bl[n * STRIDE_B + kl];
                const unsigned bl1 = Bl[n * STRIDE_B + kl + 4];
                #pragma unroll
                for (int mt = 0; mt < 2; ++mt) {
                    mma_bf16(acc[mt][nt], ah[mt][0], ah[mt][1], ah[mt][2], ah[mt][3], bh0, bh1);
                    mma_bf16(acc[mt][nt], al[mt][0], al[mt][1], al[mt][2], al[mt][3], bh0, bh1);
                    mma_bf16(acc[mt][nt], ah[mt][0], ah[mt][1], ah[mt][2], ah[mt][3], bl0, bl1);
                }
            }
        }
    }

    // ---- epilogue: C + b2 into fp32 A region ----
    #pragma unroll
    for (int mt = 0; mt < 2; ++mt) {
        const int row0 = wm * 32 + mt * 16 + gid;
        #pragma unroll
        for (int nt = 0; nt < 8; ++nt) {
            const int col = wn * 64 + nt * 8 + 2 * tig;
            const float bb0 = b2s[col], bb1 = b2s[col + 1];
            *reinterpret_cast<float2*>(&A[row0 * STRIDE_A + col]) =
                make_float2(acc[mt][nt][0] + bb0, acc[mt][nt][1] + bb1);
            *reinterpret_cast<float2*>(&A[(row0 + 8) * STRIDE_A + col]) =
                make_float2(acc[mt][nt][2] + bb0, acc[mt][nt][3] + bb1);
        }
    }
    __syncthreads();

    if (hasLN2) {
        ln_pass<0>(A, g2s, bt2s, nullptr, nullptr);
        __syncthreads();
    }

    // ---- coalesced store into strided output slots ----
    #pragma unroll 4
    for (int tok = 0; tok < TOK_PER_CTA; ++tok)
        p.out[baseS[tok] + tid] = A[tok * STRIDE_A + tid];
}

__global__ void copy_x_kernel(const float* __restrict__ x, float* __restrict__ out) {
    const int idx = blockIdx.x * blockDim.x + threadIdx.x;
    if (idx < NROWS * NX) {
        const int row = idx / NX;
        const int c = idx - row * NX;
        out[row * OUT_STRIDE + 22 * 256 + c] = x[idx];
    }
}

extern "C" void kernel_launch(void* const* d_in, const int* in_sizes, int n_in,
                              void* d_out, int out_size) {
    (void)in_sizes; (void)n_in; (void)out_size;
    const float* x = (const float*)d_in[0];

    Params p;
    p.x = x;
    p.out = (float*)d_out;
    // type 0 = pv (d_in 1..6), 1 = rot (7..12), 2 = st (21..28), 3 = pad (13..20)
    p.W1[0] = (const float*)d_in[1];  p.b1[0] = (const float*)d_in[2];
    p.g1[0] = (const float*)d_in[3];  p.bt1[0] = (const float*)d_in[4];
    p.W2[0] = (const float*)d_in[5];  p.b2[0] = (const float*)d_in[6];
    p.g2[0] = nullptr;                p.bt2[0] = nullptr;

    p.W1[1] = (const float*)d_in[7];  p.b1[1] = (const float*)d_in[8];
    p.g1[1] = (const float*)d_in[9];  p.bt1[1] = (const float*)d_in[10];
    p.W2[1] = (const float*)d_in[11]; p.b2[1] = (const float*)d_in[12];
    p.g2[1] = nullptr;                p.bt2[1] = nullptr;

    p.W1[2] = (const float*)d_in[21]; p.b1[2] = (const float*)d_in[22];
    p.g1[2] = (const float*)d_in[23]; p.bt1[2] = (const float*)d_in[24];
    p.W2[2] = (const float*)d_in[25]; p.b2[2] = (const float*)d_in[26];
    p.g2[2] = (const float*)d_in[27]; p.bt2[2] = (const float*)d_in[28];

    p.W1[3] = (const float*)d_in[13]; p.b1[3] = (const float*)d_in[14];
    p.g1[3] = (const float*)d_in[15]; p.bt1[3] = (const float*)d_in[16];
    p.W2[3] = (const float*)d_in[17]; p.b2[3] = (const float*)d_in[18];
    p.g2[3] = (const float*)d_in[19]; p.bt2[3] = (const float*)d_in[20];

    cudaFuncSetAttribute(phys_kernel,
                         cudaFuncAttributeMaxDynamicSharedMemorySize, SMEM_BYTES);
    phys_kernel<<<TOTAL_BLOCKS, 256, SMEM_BYTES>>>(p);

    const int nCopy = NROWS * NX;
    copy_x_kernel<<<(nCopy + 255) / 256, 256>>>(x, (float*)d_out);
}

// round 10
// speedup vs baseline: 2.2423x; 1.8589x over previous
#include <cuda_runtime.h>
#include <cuda_bf16.h>
#include <cstdint>

// ---------------------------------------------------------------------------
// PhysicsProjection — Round 10: mma.sync split-bf16, restructured.
// tcgen05 is unavailable (harness compiles to .target sm_100, which rejects
// tcgen05.*; R9 ptxas log). This build keeps the proven split-bf16 mma path:
//   Linear1 + LN + GELU in registers -> packed split-bf16 A tiles ->
//   C = Ahi*Bhi + Alo*Bhi + Ahi*Blo (mma.m16n8k16.bf16), 128 tok/CTA,
//   16 warps, double-buffered k32 B staging -> C via dead A smem -> LN2 ->
//   coalesced strided store.  copy_x launched FIRST so ncu captures phys.
// ---------------------------------------------------------------------------

#define NROWS 16384
#define NX    111
#define OUT_STRIDE (22 * 256 + 111)   // 5743
#define TOK 128
#define THREADS 512

#define PV_BLOCKS  2176   // 16384*17/128
#define ROT_BLOCKS 256
#define ST_BLOCKS  256
#define PAD_BLOCKS 128
#define TOTAL_BLOCKS (PV_BLOCKS + ROT_BLOCKS + ST_BLOCKS + PAD_BLOCKS) // 2816

#define STRIDE_AP 132   // packed A pair-word row stride -> bank 4*row+kp, bijective
#define STRIDE_B  20    // packed B pair-word row stride -> bank 20*n+k, bijective
#define STRIDE_C  260   // fp32 C row stride (aliases A region)

__constant__ int c_PV_START[17] = {0,3,6,43,46,49,61,64,67,74,77,80,92,95,98,105,108};
__constant__ int c_PV_SLOT[17]  = {0,1,2,4,5,6,8,9,10,12,13,14,16,17,18,20,21};

// ---- smem layout (byte offsets) ----
#define SM_A    0                        // Ah 128*132*4 = 67584
#define SM_AL   67584                    // Al 67584            (A+Al reused as C)
#define SM_B    135168                   // 2 bufs x (hi 20480 + lo 20480) = 81920
#define SM_XS   (SM_B + 40960)           // aliases buf1: 128*35*4 = 17920
#define SM_PAR  217088                   // 6 x 1024 (b1,g1,bt1,b2,g2,bt2)
#define SM_BASE 223232                   // 128 ints
#define SMEM_BYTES 223744

struct Params {
    const float* x;
    const float* W1[4];
    const float* b1[4];
    const float* g1[4];
    const float* bt1[4];
    const float* W2[4];
    const float* b2[4];
    const float* g2[4];
    const float* bt2[4];
    float* out;
};

// ---- helpers ----
__device__ __forceinline__ uint32_t smem_u32(const void* p) {
    uint32_t a;
    asm("{ .reg .u64 t; cvta.to.shared.u64 t, %1; cvt.u32.u64 %0, t; }" : "=r"(a) : "l"(p));
    return a;
}
__device__ __forceinline__ unsigned bf16x2_lo(float l0, float l1) {
    unsigned w;
    asm("cvt.rn.bf16x2.f32 %0, %1, %2;" : "=r"(w) : "f"(l1), "f"(l0));
    return w;
}
__device__ __forceinline__ void sts128(uint32_t addr, const uint32_t* v) {
    asm volatile("st.shared.v4.b32 [%0], {%1,%2,%3,%4};"
                 :: "r"(addr), "r"(v[0]), "r"(v[1]), "r"(v[2]), "r"(v[3]) : "memory");
}
__device__ __forceinline__ void mma_bf16(float* c, unsigned a0, unsigned a1,
                                         unsigned a2, unsigned a3,
                                         unsigned b0, unsigned b1) {
    asm("mma.sync.aligned.m16n8k16.row.col.f32.bf16.bf16.f32 "
        "{%0,%1,%2,%3}, {%4,%5,%6,%7}, {%8,%9}, {%0,%1,%2,%3};"
        : "+f"(c[0]), "+f"(c[1]), "+f"(c[2]), "+f"(c[3])
        : "r"(a0), "r"(a1), "r"(a2), "r"(a3), "r"(b0), "r"(b1));
}
__device__ __forceinline__ void split_pack(const float* e, uint32_t* hw, uint32_t* lw) {
    #pragma unroll
    for (int jj = 0; jj < 4; ++jj) {
        const unsigned u0 = __float_as_uint(e[2 * jj]);
        const unsigned u1 = __float_as_uint(e[2 * jj + 1]);
        hw[jj] = __byte_perm(u0, u1, 0x7632);
        const float l0 = e[2 * jj]     - __uint_as_float(u0 & 0xFFFF0000u);
        const float l1 = e[2 * jj + 1] - __uint_as_float(u1 & 0xFFFF0000u);
        lw[jj] = bf16x2_lo(l0, l1);
    }
}

__global__ void __launch_bounds__(THREADS, 1)
phys_kernel(Params p) {
    extern __shared__ char smem[];
    const uint32_t sb = smem_u32(smem);
    float* xs   = reinterpret_cast<float*>(smem + SM_XS);
    float* b1s  = reinterpret_cast<float*>(smem + SM_PAR);
    float* g1s  = reinterpret_cast<float*>(smem + SM_PAR + 1024);
    float* bt1s = reinterpret_cast<float*>(smem + SM_PAR + 2048);
    float* b2s  = reinterpret_cast<float*>(smem + SM_PAR + 3072);
    float* g2s  = reinterpret_cast<float*>(smem + SM_PAR + 4096);
    float* bt2s = reinterpret_cast<float*>(smem + SM_PAR + 5120);
    int*   baseS = reinterpret_cast<int*>(smem + SM_BASE);
    unsigned* Ah = reinterpret_cast<unsigned*>(smem + SM_A);
    unsigned* Al = reinterpret_cast<unsigned*>(smem + SM_AL);
    float* C = reinterpret_cast<float*>(smem + SM_A);     // alias, post-GEMM

    const int tid  = threadIdx.x;
    const int lane = tid & 31;
    const int warp = tid >> 5;
    const int bid  = blockIdx.x;

    int type, tokBase;
    if (bid < PV_BLOCKS)                       { type = 0; tokBase = bid * TOK; }
    else if (bid < PV_BLOCKS + ROT_BLOCKS)     { type = 1; tokBase = (bid - PV_BLOCKS) * TOK; }
    else if (bid < PV_BLOCKS + ROT_BLOCKS + ST_BLOCKS)
                                               { type = 2; tokBase = (bid - PV_BLOCKS - ROT_BLOCKS) * TOK; }
    else                                       { type = 3; tokBase = (bid - PV_BLOCKS - ROT_BLOCKS - ST_BLOCKS) * TOK; }

    const int din = (type == 0) ? 3 : (type == 1) ? 9 : (type == 2) ? 4 : 34;
    const bool hasLN2 = (type >= 2);

    // ---- params / baseS / gather ----
    if (tid < 256) {
        b1s[tid]  = p.b1[type][tid];
        g1s[tid]  = p.g1[type][tid];
        bt1s[tid] = p.bt1[type][tid];
        b2s[tid]  = p.b2[type][tid];
        if (hasLN2) { g2s[tid] = p.g2[type][tid]; bt2s[tid] = p.bt2[type][tid]; }
    }
    if (tid < TOK) {
        const int t = tokBase + tid;
        int row, slot;
        if (type == 0)      { row = t / 17; slot = c_PV_SLOT[t - row * 17]; }
        else if (type == 1) { row = t >> 1; slot = (t & 1) ? 15 : 7; }
        else if (type == 2) { row = t >> 1; slot = (t & 1) ? 19 : 11; }
        else                { row = t;      slot = 3; }
        baseS[tid] = row * OUT_STRIDE + slot * 256;
    }
    const int totalFeat = TOK * din;
    for (int idx = tid; idx < totalFeat; idx += THREADS) {
        const int tok = idx / din;
        const int i   = idx - tok * din;
        const int t   = tokBase + tok;
        int row, col;
        if (type == 0)      { row = t / 17; col = c_PV_START[t - row * 17] + i; }
        else if (type == 1) { row = t >> 1; col = ((t & 1) ? 83 : 52) + i; }
        else if (type == 2) { row = t >> 1; col = ((t & 1) ? 101 : 70) + i; }
        else                { row = t;      col = 9 + i; }
        xs[tok * 35 + i] = p.x[row * NX + col];
    }
    __syncthreads();

    // ---- Linear1 in registers: warp owns tokens 8w..8w+7, lane owns cols 8l..8l+7
    {
        float acc1[8][8];
        const float* W1g = p.W1[type];
        const float4 bA = *reinterpret_cast<const float4*>(b1s + 8 * lane);
        const float4 bB = *reinterpret_cast<const float4*>(b1s + 8 * lane + 4);
        #pragma unroll
        for (int t = 0; t < 8; ++t) {
            acc1[t][0]=bA.x; acc1[t][1]=bA.y; acc1[t][2]=bA.z; acc1[t][3]=bA.w;
            acc1[t][4]=bB.x; acc1[t][5]=bB.y; acc1[t][6]=bB.z; acc1[t][7]=bB.w;
        }
        for (int i = 0; i < din; ++i) {
            const float4 wa = *reinterpret_cast<const float4*>(W1g + i * 256 + 8 * lane);
            const float4 wb = *reinterpret_cast<const float4*>(W1g + i * 256 + 8 * lane + 4);
            #pragma unroll
            for (int t = 0; t < 8; ++t) {
                const float xv = xs[(8 * warp + t) * 35 + i];
                acc1[t][0] += xv * wa.x; acc1[t][1] += xv * wa.y;
                acc1[t][2] += xv * wa.z; acc1[t][3] += xv * wa.w;
                acc1[t][4] += xv * wb.x; acc1[t][5] += xv * wb.y;
                acc1[t][6] += xv * wb.z; acc1[t][7] += xv * wb.w;
            }
        }

        // ---- LN + GELU + split-bf16 pack -> Ah/Al (stride 132 pair words) ----
        #pragma unroll
        for (int t = 0; t < 8; ++t) {
            const int r = 8 * warp + t;
            float s = 0.f, s2 = 0.f;
            #pragma unroll
            for (int c = 0; c < 8; ++c) { s += acc1[t][c]; s2 += acc1[t][c] * acc1[t][c]; }
            #pragma unroll
            for (int o = 16; o > 0; o >>= 1) {
                s  += __shfl_xor_sync(0xffffffffu, s, o);
                s2 += __shfl_xor_sync(0xffffffffu, s2, o);
            }
            const float mean = s * (1.0f / 256.0f);
            const float var  = s2 * (1.0f / 256.0f) - mean * mean;
            const float rstd = rsqrtf(var + 1e-5f);
            float v[8];
            #pragma unroll
            for (int c = 0; c < 8; ++c) {
                const int j = 8 * lane + c;
                float u = (acc1[t][c] - mean) * rstd * g1s[j] + bt1s[j];
                v[c] = 0.5f * u * (1.0f + erff(u * 0.70710678118654752f));
            }
            uint32_t hw[4], lw[4];
            split_pack(v, hw, lw);
            const uint32_t ao = (uint32_t)(r * STRIDE_AP + 4 * lane) * 4u;
            sts128(sb + SM_A + ao, hw);
            sts128(sb + SM_AL + ao, lw);
        }
    }
    __syncthreads();   // xs (aliasing buf1) dead; A tiles visible to all warps

    // ---- GEMM: C[128,256] = A @ W2, split-bf16, double-buffered k32 chunks ----
    const int wm = warp >> 2;       // 0..3 : rows wm*32..+31
    const int wn = warp & 3;        // 0..3 : cols wn*64..+63
    const int gid = lane >> 2;
    const int tig = lane & 3;
    const float* W2g = p.W2[type];

    float acc[2][8][4];
    #pragma unroll
    for (int mt = 0; mt < 2; ++mt)
        #pragma unroll
        for (int nt = 0; nt < 8; ++nt)
            #pragma unroll
            for (int q = 0; q < 4; ++q) acc[mt][nt][q] = 0.f;

    // staging tasks: task r in {0,1}: n = (tid+512r)&255, kq = (tid+512r)>>8 (0..3)
    const int n0 = tid & 255;
    const int kq0 = tid >> 8;        // 0..1
    float e[2][8];

    // prefetch chunk 0
    #pragma unroll
    for (int r = 0; r < 2; ++r) {
        const int kq = kq0 + 2 * r;
        #pragma unroll
        for (int j = 0; j < 8; ++j)
            e[r][j] = W2g[(kq * 8 + j) * 256 + n0];
    }

    for (int ch = 0; ch < 8; ++ch) {
        const uint32_t bufb = sb + SM_B + (uint32_t)(ch & 1) * 40960u;
        // convert + store staged chunk (uses e loaded last iteration)
        #pragma unroll
        for (int r = 0; r < 2; ++r) {
            const int kq = kq0 + 2 * r;
            uint32_t hw[4], lw[4];
            split_pack(e[r], hw, lw);
            const uint32_t addr = (uint32_t)(n0 * STRIDE_B + kq * 4) * 4u;
            sts128(bufb + addr, hw);
            sts128(bufb + 20480u + addr, lw);
        }
        __syncthreads();
        // prefetch next chunk while mma runs
        if (ch < 7) {
            #pragma unroll
            for (int r = 0; r < 2; ++r) {
                const int kq = kq0 + 2 * r;
                #pragma unroll
                for (int j = 0; j < 8; ++j)
                    e[r][j] = W2g[((ch + 1) * 32 + kq * 8 + j) * 256 + n0];
            }
        }
        unsigned* Bh = reinterpret_cast<unsigned*>(smem + SM_B + (ch & 1) * 40960);
        unsigned* Bl = Bh + 5120;   // +20480 bytes
        #pragma unroll
        for (int s = 0; s < 2; ++s) {
            const int kp0 = ch * 16 + 8 * s + tig;   // global A k-pair
            const int kl  = 8 * s + tig;             // chunk-local B k-pair
            unsigned ah[2][4], al[2][4];
            #pragma unroll
            for (int mt = 0; mt < 2; ++mt) {
                const int mrow = wm * 32 + mt * 16;
                ah[mt][0] = Ah[(mrow + gid)     * STRIDE_AP + kp0];
                ah[mt][1] = Ah[(mrow + gid + 8) * STRIDE_AP + kp0];
                ah[mt][2] = Ah[(mrow + gid)     * STRIDE_AP + kp0 + 4];
                ah[mt][3] = Ah[(mrow + gid + 8) * STRIDE_AP + kp0 + 4];
                al[mt][0] = Al[(mrow + gid)     * STRIDE_AP + kp0];
                al[mt][1] = Al[(mrow + gid + 8) * STRIDE_AP + kp0];
                al[mt][2] = Al[(mrow + gid)     * STRIDE_AP + kp0 + 4];
                al[mt][3] = Al[(mrow + gid + 8) * STRIDE_AP + kp0 + 4];
            }
            #pragma unroll
            for (int nt = 0; nt < 8; ++nt) {
                const int n = wn * 64 + nt * 8 + gid;
                const unsigned bh0 = Bh[n * STRIDE_B + kl];
                const unsigned bh1 = Bh[n * STRIDE_B + kl + 4];
                const unsigned bl0 = Bl[n * STRIDE_B + kl];
                const unsigned bl1 = Bl[n * STRIDE_B + kl + 4];
                #pragma unroll
                for (int mt = 0; mt < 2; ++mt) {
                    mma_bf16(acc[mt][nt], ah[mt][0], ah[mt][1], ah[mt][2], ah[mt][3], bh0, bh1);
                    mma_bf16(acc[mt][nt], al[mt][0], al[mt][1], al[mt][2], al[mt][3], bh0, bh1);
                    mma_bf16(acc[mt][nt], ah[mt][0], ah[mt][1], ah[mt][2], ah[mt][3], bl0, bl1);
                }
            }
        }
    }
    __syncthreads();   // all A reads done; A region becomes C

    // ---- epilogue: C + b2 into (dead) A region ----
    #pragma unroll
    for (int mt = 0; mt < 2; ++mt) {
        const int row0 = wm * 32 + mt * 16 + gid;
        #pragma unroll
        for (int nt = 0; nt < 8; ++nt) {
            const int col = wn * 64 + nt * 8 + 2 * tig;
            const float bb0 = b2s[col], bb1 = b2s[col + 1];
            *reinterpret_cast<float2*>(&C[row0 * STRIDE_C + col]) =
                make_float2(acc[mt][nt][0] + bb0, acc[mt][nt][1] + bb1);
            *reinterpret_cast<float2*>(&C[(row0 + 8) * STRIDE_C + col]) =
                make_float2(acc[mt][nt][2] + bb0, acc[mt][nt][3] + bb1);
        }
    }
    __syncthreads();

    if (hasLN2) {   // LN over each row of C (16 warps x 8 rows)
        #pragma unroll
        for (int r = 0; r < 8; ++r) {
            const int tok = warp * 8 + r;
            float v[8];
            float s = 0.f, s2 = 0.f;
            #pragma unroll
            for (int c = 0; c < 8; ++c) {
                v[c] = C[tok * STRIDE_C + lane + (c << 5)];
                s += v[c];
                s2 += v[c] * v[c];
            }
            #pragma unroll
            for (int o = 16; o > 0; o >>= 1) {
                s  += __shfl_xor_sync(0xffffffffu, s, o);
                s2 += __shfl_xor_sync(0xffffffffu, s2, o);
            }
            const float mean = s * (1.0f / 256.0f);
            const float var  = s2 * (1.0f / 256.0f) - mean * mean;
            const float rstd = rsqrtf(var + 1e-5f);
            #pragma unroll
            for (int c = 0; c < 8; ++c) {
                const int j = lane + (c << 5);
                C[tok * STRIDE_C + j] = (v[c] - mean) * rstd * g2s[j] + bt2s[j];
            }
        }
        __syncthreads();
    }

    // ---- coalesced store into strided output slots ----
    {
        const int half = tid >> 8;       // 0..1
        const int col  = tid & 255;
        #pragma unroll 4
        for (int t = 0; t < 64; ++t) {
            const int tok = 2 * t + half;
            p.out[baseS[tok] + col] = C[tok * STRIDE_C + col];
        }
    }
}

__global__ void copy_x_kernel(const float* __restrict__ x, float* __restrict__ out) {
    const int idx = blockIdx.x * blockDim.x + threadIdx.x;
    if (idx < NROWS * NX) {
        const int row = idx / NX;
        const int c = idx - row * NX;
        out[row * OUT_STRIDE + 22 * 256 + c] = x[idx];
    }
}

extern "C" void kernel_launch(void* const* d_in, const int* in_sizes, int n_in,
                              void* d_out, int out_size) {
    (void)in_sizes; (void)n_in; (void)out_size;
    const float* x = (const float*)d_in[0];

    Params p;
    p.x = x;
    p.out = (float*)d_out;
    // type 0 = pv (d_in 1..6), 1 = rot (7..12), 2 = st (21..28), 3 = pad (13..20)
    p.W1[0] = (const float*)d_in[1];  p.b1[0] = (const float*)d_in[2];
    p.g1[0] = (const float*)d_in[3];  p.bt1[0] = (const float*)d_in[4];
    p.W2[0] = (const float*)d_in[5];  p.b2[0] = (const float*)d_in[6];
    p.g2[0] = nullptr;                p.bt2[0] = nullptr;

    p.W1[1] = (const float*)d_in[7];  p.b1[1] = (const float*)d_in[8];
    p.g1[1] = (const float*)d_in[9];  p.bt1[1] = (const float*)d_in[10];
    p.W2[1] = (const float*)d_in[11]; p.b2[1] = (const float*)d_in[12];
    p.g2[1] = nullptr;                p.bt2[1] = nullptr;

    p.W1[2] = (const float*)d_in[21]; p.b1[2] = (const float*)d_in[22];
    p.g1[2] = (const float*)d_in[23]; p.bt1[2] = (const float*)d_in[24];
    p.W2[2] = (const float*)d_in[25]; p.b2[2] = (const float*)d_in[26];
    p.g2[2] = (const float*)d_in[27]; p.bt2[2] = (const float*)d_in[28];

    p.W1[3] = (const float*)d_in[13]; p.b1[3] = (const float*)d_in[14];
    p.g1[3] = (const float*)d_in[15]; p.bt1[3] = (const float*)d_in[16];
    p.W2[3] = (const float*)d_in[17]; p.b2[3] = (const float*)d_in[18];
    p.g2[3] = (const float*)d_in[19]; p.bt2[3] = (const float*)d_in[20];

    // copy_x first: ncu (-s 5 -c 1) then captures phys_kernel as launch #6
    const int nCopy = NROWS * NX;
    copy_x_kernel<<<(nCopy + 255) / 256, 256>>>(x, (float*)d_out);

    cudaFuncSetAttribute(phys_kernel,
                         cudaFuncAttributeMaxDynamicSharedMemorySize, SMEM_BYTES);
    phys_kernel<<<TOTAL_BLOCKS, THREADS, SMEM_BYTES>>>(p);
}